// round 16
// baseline (speedup 1.0000x reference)
#include <cuda_runtime.h>
#include <cuda_bf16.h>
#include <math.h>

// Problem constants
#define BB    128
#define KTOT  8194             // pos (2) + neg (8192)
#define NMEM  100000
#define TAU_INV 14.2857142857142857f   // 1/0.07
#define KDT_F 3.0f
#define N4    (NMEM * 32)      // float4 per mem = 3,200,000
#define SPLITS 27
#define GATHB 432              // 432 CTAs x 8 warps = 3456 = 128*27 warp tasks
#define NG8   ((KTOT + 7) / 8) // 1025 groups of 8 k's

// bf16 mirror, row-interleaved: row r = [mem0 r: 16 uint4][mem1 r: 16 uint4]
__device__ uint4 g_membf[NMEM * 32];

// Per-(b,split) partials: j*3+0 = sum e^{v/T}, +1 = sum e^v, +2 = sum e^{v/T}(v-o)
// j: 0=cij, 1=cji, 2=intra0, 3=intra1
__device__ float g_part2[BB][SPLITS][12];
// Per-b specials: [a0, c0, a1, c1, ia1, ib1]
__device__ float g_spec[BB][6];

// ---------------------------------------------------------------------------
// Prep: one streaming pass over fp32 mems -> fp32 copy in out (L2-bypass) +
// bf16 mirror (normal stores -> L2-resident). One task per thread.
// ---------------------------------------------------------------------------
__global__ void __launch_bounds__(256)
prep_kernel(const float4* __restrict__ m0, const float4* __restrict__ m1,
            float4* __restrict__ dst)   // = out + 4
{
    const int u = blockIdx.x * blockDim.x + threadIdx.x;   // [0, NMEM*16)
    if (u >= NMEM * 16) return;
    const int r = u >> 4, s = u & 15;
    const size_t i0 = (size_t)r * 32 + s * 2;

    float4 a0 = __ldcs(m0 + i0), a1 = __ldcs(m0 + i0 + 1);
    float4 c0 = __ldcs(m1 + i0), c1 = __ldcs(m1 + i0 + 1);
    __stcs(dst + i0,          a0);
    __stcs(dst + i0 + 1,      a1);
    __stcs(dst + N4 + i0,     c0);
    __stcs(dst + N4 + i0 + 1, c1);

    union { uint4 u4; __nv_bfloat162 h[4]; } p;
    p.h[0] = __float22bfloat162_rn(make_float2(a0.x, a0.y));
    p.h[1] = __float22bfloat162_rn(make_float2(a0.z, a0.w));
    p.h[2] = __float22bfloat162_rn(make_float2(a1.x, a1.y));
    p.h[3] = __float22bfloat162_rn(make_float2(a1.z, a1.w));
    g_membf[(size_t)r * 32 + s] = p.u4;
    p.h[0] = __float22bfloat162_rn(make_float2(c0.x, c0.y));
    p.h[1] = __float22bfloat162_rn(make_float2(c0.z, c0.w));
    p.h[2] = __float22bfloat162_rn(make_float2(c1.x, c1.y));
    p.h[3] = __float22bfloat162_rn(make_float2(c1.z, c1.w));
    g_membf[(size_t)r * 32 + 16 + s] = p.u4;
}

// 8 bf16 (one uint4) dotted against two fp32 emb fragments
__device__ __forceinline__ void dot8(uint4 q,
                                     float4 ej0, float4 ej1,
                                     float4 ek0, float4 ek1,
                                     float& sj, float& sk)
{
    __nv_bfloat162* h = reinterpret_cast<__nv_bfloat162*>(&q);
    float2 f0 = __bfloat1622float2(h[0]);
    float2 f1 = __bfloat1622float2(h[1]);
    float2 f2 = __bfloat1622float2(h[2]);
    float2 f3 = __bfloat1622float2(h[3]);
    sj += f0.x*ej0.x + f0.y*ej0.y + f1.x*ej0.z + f1.y*ej0.w
        + f2.x*ej1.x + f2.y*ej1.y + f3.x*ej1.z + f3.y*ej1.w;
    sk += f0.x*ek0.x + f0.y*ek0.y + f1.x*ek0.z + f1.y*ek0.w
        + f2.x*ek1.x + f2.y*ek1.y + f3.x*ek1.z + f3.y*ek1.w;
}

// ---------------------------------------------------------------------------
// Gather: ONE WARP per (b, split) task, SPLITS=27 -> 3456 warp tasks in
// 432 CTAs = one full wave at occ 3 (no wave quantization). Inner loop is
// the validated R8/R15 body: quarter-warp per k, 2 k's unrolled
// (8 LDG.128/lane in flight), exp-sums folded inline.
// ---------------------------------------------------------------------------
__global__ void __launch_bounds__(256, 3)
gather_kernel(const float* __restrict__ emb0,
              const float* __restrict__ emb1,
              const int*   __restrict__ pos_idx,
              const int*   __restrict__ neg_idx)
{
    const int tid  = threadIdx.x;
    const int lane = tid & 31;
    const int warp = tid >> 5;            // 0..7
    const int wg    = blockIdx.x * 8 + warp;   // 0..3455
    const int b     = wg & (BB - 1);
    const int split = wg >> 7;            // 0..SPLITS-1
    const int grp   = lane >> 3;          // quarter-warp: one k each
    const int gl    = lane & 7;
    const int j     = lane & 3;           // accumulator array for this lane

    // emb fragments: lane covers dims [(i*8+gl)*8, +8) for i in {0,1}
    const float4* e0p = reinterpret_cast<const float4*>(emb0) + b * 32;
    const float4* e1p = reinterpret_cast<const float4*>(emb1) + b * 32;
    float4 e0r[2][2], e1r[2][2];
#pragma unroll
    for (int i = 0; i < 2; i++)
#pragma unroll
        for (int q = 0; q < 2; q++) {
            e0r[i][q] = e0p[(i*8 + gl)*2 + q];
            e1r[i][q] = e1p[(i*8 + gl)*2 + q];
        }

    float accT = 0.f, acc1 = 0.f, accW = 0.f;

    for (int gg = split; gg < NG8; gg += SPLITS) {
        const int kb = gg * 8;
        const int k0 = kb + grp;          // first 4-k group
        const int k1 = kb + 4 + grp;      // second 4-k group
        const bool v0 = (k0 < KTOT), v1 = (k1 < KTOT);
        int r0 = 0, r1 = 0;
        if (v0) r0 = (k0 < 2) ? pos_idx[b*2 + k0] : neg_idx[b*8192 + (k0 - 2)];
        if (v1) r1 = (k1 < 2) ? pos_idx[b*2 + k1] : neg_idx[b*8192 + (k1 - 2)];
        const uint4* R0 = g_membf + (size_t)r0 * 32;
        const uint4* R1 = g_membf + (size_t)r1 * 32;

        // 8 independent 16B loads (quarter-warp => 128B lines)
        uint4 q0 = R0[gl],      q1 = R0[8 + gl];
        uint4 q2 = R0[16 + gl], q3 = R0[24 + gl];
        uint4 q4 = R1[gl],      q5 = R1[8 + gl];
        uint4 q6 = R1[16 + gl], q7 = R1[24 + gl];

        float s[8] = {0.f,0.f,0.f,0.f,0.f,0.f,0.f,0.f};
        // group 0: s[0]=cij, s[1]=cji, s[2]=intra0, s[3]=intra1
        dot8(q0, e1r[0][0], e1r[0][1], e0r[0][0], e0r[0][1], s[0], s[2]);
        dot8(q1, e1r[1][0], e1r[1][1], e0r[1][0], e0r[1][1], s[0], s[2]);
        dot8(q2, e0r[0][0], e0r[0][1], e1r[0][0], e1r[0][1], s[1], s[3]);
        dot8(q3, e0r[1][0], e0r[1][1], e1r[1][0], e1r[1][1], s[1], s[3]);
        // group 1
        dot8(q4, e1r[0][0], e1r[0][1], e0r[0][0], e0r[0][1], s[4], s[6]);
        dot8(q5, e1r[1][0], e1r[1][1], e0r[1][0], e0r[1][1], s[4], s[6]);
        dot8(q6, e0r[0][0], e0r[0][1], e1r[0][0], e1r[0][1], s[5], s[7]);
        dot8(q7, e0r[1][0], e0r[1][1], e1r[1][0], e1r[1][1], s[5], s[7]);

        // interleaved quarter-warp reduce of all 8 sums
#pragma unroll
        for (int o = 4; o; o >>= 1)
#pragma unroll
            for (int qq = 0; qq < 8; qq++)
                s[qq] += __shfl_xor_sync(0xffffffffu, s[qq], o);

        const float la0  = s[0]*TAU_INV, lc0  = s[1]*TAU_INV;
        const float lia0 = s[2]*TAU_INV, lib0 = s[3]*TAU_INV;
        const float la1  = s[4]*TAU_INV, lc1  = s[5]*TAU_INV;
        const float lia1 = s[6]*TAU_INV, lib1 = s[7]*TAU_INV;

        if (gg == 0) {                    // split-0 warps only (one per b)
            if (lane == 0) { g_spec[b][0] = la0; g_spec[b][1] = lc0; }  // k=0
            if (lane == 8) { g_spec[b][2] = la0; g_spec[b][3] = lc0;    // k=1
                             g_spec[b][4] = lia0; g_spec[b][5] = lib0; }
        }

        float v0v, o0v, v1v, o1v;
        if      (j == 0) { v0v = la0;  o0v = lc0;  v1v = la1;  o1v = lc1;  }
        else if (j == 1) { v0v = lc0;  o0v = la0;  v1v = lc1;  o1v = la1;  }
        else if (j == 2) { v0v = lia0; o0v = lib0; v1v = lia1; o1v = lib1; }
        else             { v0v = lib0; o0v = lia0; v1v = lib1; o1v = lia1; }
        const bool val0 = (j < 2) ? v0 : (v0 && k0 >= 1);  // intra excludes k=0
        const bool val1 = v1;                              // k1 >= 4 always

        const float e30 = val0 ? __expf(v0v * (1.0f/KDT_F)) : 0.f;
        const float e31 = val1 ? __expf(v1v * (1.0f/KDT_F)) : 0.f;
        accT += e30 + e31;
        acc1 += e30*e30*e30 + e31*e31*e31;   // exp(v) = exp(v/3)^3
        accW += e30*(v0v - o0v) + e31*(v1v - o1v);
    }

    // xor4 folds the gl/gl+4 duplication (exact x2, halved below);
    // xor 8,16 fold the k-quarters. Lanes 0..3 then hold totals for j=0..3.
#pragma unroll
    for (int o = 4; o <= 16; o <<= 1) {
        accT += __shfl_xor_sync(0xffffffffu, accT, o);
        acc1 += __shfl_xor_sync(0xffffffffu, acc1, o);
        accW += __shfl_xor_sync(0xffffffffu, accW, o);
    }
    if (lane < 4) {
        g_part2[b][split][lane*3 + 0] = accT * 0.5f;
        g_part2[b][split][lane*3 + 1] = acc1 * 0.5f;
        g_part2[b][split][lane*3 + 2] = accW * 0.5f;
    }
}

// ---------------------------------------------------------------------------
// Finalize: CTA 0 reduces partials into the 4 scalars; CTAs 1..32 apply the
// momentum update (p0 values staged in SMEM for the last-wins dedup scan).
// ---------------------------------------------------------------------------
__global__ void __launch_bounds__(256)
finalize_kernel(const float* __restrict__ emb0,
                const float* __restrict__ emb1,
                const float4* __restrict__ mem0,
                const float4* __restrict__ mem1,
                const int*   __restrict__ pos_idx,
                float* __restrict__ out)
{
    if (blockIdx.x == 0) {
        const int t = threadIdx.x;
        float raw[4] = {0.f, 0.f, 0.f, 0.f};
        if (t < BB) {
            float s[12];
#pragma unroll
            for (int q = 0; q < 12; q++) {
                float acc = 0.f;
                for (int sp = 0; sp < SPLITS; sp++) acc += g_part2[t][sp][q];
                s[q] = acc;
            }
            const float sAT = s[0],  sA  = s[1],  w1 = s[2];
            const float sBT = s[3],  sB  = s[4],  w0 = s[5];
            const float sIaT= s[6],  sIa = s[7],  w3 = s[8];
            const float sIbT= s[9],  sIb = s[10], w2 = s[11];
            const float LA  = logf(sA),  LB  = logf(sB);
            const float LIa = logf(sIa), LIb = logf(sIb);
            const float a0 = g_spec[t][0], c0 = g_spec[t][1];
            const float a1 = g_spec[t][2], c1 = g_spec[t][3];
            const float ia1 = g_spec[t][4], ib1 = g_spec[t][5];
            raw[0] = -(ia1 - LIa) - (ib1 - LIb);                       // vcl
            raw[1] = KDT_F * (w2 / sIbT + w3 / sIaT);                  // soft_vcl
            raw[2] = -(0.5f*(a0+a1) - LA) - (0.5f*(c0+c1) - LB);       // icl
            raw[3] = KDT_F * (w0 / sBT + w1 / sAT);                    // soft_icl
        }
        __shared__ float scr[8][4];
#pragma unroll
        for (int q = 0; q < 4; q++) {
            float v = raw[q];
#pragma unroll
            for (int o = 16; o; o >>= 1) v += __shfl_xor_sync(0xffffffffu, v, o);
            if ((t & 31) == 0) scr[t >> 5][q] = v;
        }
        __syncthreads();
        if (t == 0) {
#pragma unroll
            for (int q = 0; q < 4; q++) {
                float v = 0.f;
                for (int w = 0; w < 8; w++) v += scr[w][q];
                out[q] = v / (float)BB;
            }
        }
        return;
    }

    // ---- momentum update: 256 warp tasks = (b, net), p0 staged in SMEM ----
    __shared__ int sp0[BB];
    for (int i = threadIdx.x; i < BB; i += 256) sp0[i] = pos_idx[i * 2];
    __syncthreads();

    const int w    = (blockIdx.x - 1) * 8 + (threadIdx.x >> 5);  // 0..255
    const int lane = threadIdx.x & 31;
    const int b    = w & (BB - 1);
    const int net  = w >> 7;
    const int r    = sp0[b];
    for (int bp = b + 1; bp < BB; bp++)
        if (sp0[bp] == r) return;        // a later b overwrites (last-wins)

    const float4* mem  = net ? mem1 : mem0;
    const float4* embp = reinterpret_cast<const float4*>(net ? emb1 : emb0);
    float4* dst = reinterpret_cast<float4*>(out + 4) + (size_t)net * N4;

    float4 m = mem[(size_t)r * 32 + lane];
    float4 e = embp[b * 32 + lane];
    float4 u;
    u.x = 0.5f * (m.x + e.x);    // MOM = 0.5
    u.y = 0.5f * (m.y + e.y);
    u.z = 0.5f * (m.z + e.z);
    u.w = 0.5f * (m.w + e.w);
    float s2 = u.x*u.x + u.y*u.y + u.z*u.z + u.w*u.w;
#pragma unroll
    for (int o = 16; o; o >>= 1) s2 += __shfl_xor_sync(0xffffffffu, s2, o);
    const float inv = 1.0f / sqrtf(s2);
    u.x *= inv; u.y *= inv; u.z *= inv; u.w *= inv;
    dst[(size_t)r * 32 + lane] = u;
}

// ---------------------------------------------------------------------------
extern "C" void kernel_launch(void* const* d_in, const int* in_sizes, int n_in,
                              void* d_out, int out_size)
{
    const float* emb0    = (const float*)d_in[0];
    const float* emb1    = (const float*)d_in[1];
    const float* mem0    = (const float*)d_in[2];
    const float* mem1    = (const float*)d_in[3];
    const int*   pos_idx = (const int*)  d_in[4];
    const int*   neg_idx = (const int*)  d_in[5];
    float* out = (float*)d_out;

    // out layout: [vcl, soft_vcl, icl, soft_icl, new_mem0, new_mem1]
    prep_kernel<<<(NMEM*16 + 255)/256, 256>>>((const float4*)mem0,
                                              (const float4*)mem1,
                                              (float4*)(out + 4));
    gather_kernel<<<GATHB, 256>>>(emb0, emb1, pos_idx, neg_idx);
    finalize_kernel<<<33, 256>>>(emb0, emb1,
                                 (const float4*)mem0, (const float4*)mem1,
                                 pos_idx, out);
}